// round 2
// baseline (speedup 1.0000x reference)
#include <cuda_runtime.h>

#define N_NODES 50000
#define N_EDGES 200000
#define N_TASK  10000
#define DDIM    64
#define HC      256   // H*C = 4*64

// ---------------- scratch (device globals; no allocations) ----------------
__device__ __align__(16) float g_q [N_NODES * HC];
__device__ __align__(16) float g_k [N_NODES * HC];
__device__ __align__(16) float g_v [N_NODES * HC];
__device__ __align__(16) float g_xr[N_NODES * DDIM];
__device__ __align__(16) float g_hf[N_NODES * DDIM];
__device__ int g_flag[N_NODES];
__device__ int g_deg [N_NODES];
__device__ int g_start[N_NODES + 1];
__device__ int g_cursor[N_NODES];
__device__ int g_adj[N_EDGES];

// ---------------- small setup kernels ----------------
__global__ void zero_kernel() {
    int i = blockIdx.x * blockDim.x + threadIdx.x;
    if (i < N_NODES) { g_flag[i] = 0; g_deg[i] = 0; }
}

__global__ void flag_kernel(const int* __restrict__ task) {
    int t = blockIdx.x * blockDim.x + threadIdx.x;
    if (t < N_TASK) g_flag[task[t]] = 1;
}

__global__ void degree_kernel(const int* __restrict__ dst) {
    int e = blockIdx.x * blockDim.x + threadIdx.x;
    if (e < N_EDGES) {
        int dn = dst[e];
        if (g_flag[dn]) atomicAdd(&g_deg[dn], 1);
    }
}

// single-block exclusive scan over g_deg -> g_start / g_cursor
__global__ void scan_kernel() {
    __shared__ int wsum[32];
    __shared__ int carry_s;
    int tid = threadIdx.x, lane = tid & 31, wid = tid >> 5;
    if (tid == 0) carry_s = 0;
    __syncthreads();
    for (int base = 0; base < N_NODES; base += 1024) {
        int i = base + tid;
        int v = (i < N_NODES) ? g_deg[i] : 0;
        int xv = v;
        #pragma unroll
        for (int o = 1; o < 32; o <<= 1) {
            int y = __shfl_up_sync(0xffffffffu, xv, o);
            if (lane >= o) xv += y;
        }
        if (lane == 31) wsum[wid] = xv;
        __syncthreads();
        if (wid == 0) {
            int s = wsum[lane];
            #pragma unroll
            for (int o = 1; o < 32; o <<= 1) {
                int y = __shfl_up_sync(0xffffffffu, s, o);
                if (lane >= o) s += y;
            }
            wsum[lane] = s;
        }
        __syncthreads();
        int woff  = (wid > 0) ? wsum[wid - 1] : 0;
        int incl  = xv + woff;
        int c     = carry_s;
        int total = wsum[31];
        if (i < N_NODES) {
            int excl = c + incl - v;
            g_start[i]  = excl;
            g_cursor[i] = excl;
        }
        __syncthreads();
        if (tid == 0) carry_s = c + total;
        __syncthreads();
    }
    if (threadIdx.x == 0) g_start[N_NODES] = carry_s;
}

__global__ void scatter_kernel(const int* __restrict__ srcArr,
                               const int* __restrict__ dstArr) {
    int e = blockIdx.x * blockDim.x + threadIdx.x;
    if (e < N_EDGES) {
        int dn = dstArr[e];
        if (g_flag[dn]) {
            int p = atomicAdd(&g_cursor[dn], 1);
            g_adj[p] = srcArr[e];
        }
    }
}

// ---------------- fused embed-gather GEMM: [q|k|v|xr] = emb[x] @ W + b ----
// Tiles: 64 rows x 64 cols, K=64. blockIdx.y selects which weight / column tile.
__global__ __launch_bounds__(256) void gemm_kernel(
    const int*   __restrict__ x,   const float* __restrict__ emb,
    const float* __restrict__ Wq,  const float* __restrict__ bq,
    const float* __restrict__ Wk,  const float* __restrict__ bk,
    const float* __restrict__ Wv,  const float* __restrict__ bv,
    const float* __restrict__ Ws,  const float* __restrict__ bs)
{
    __shared__ __align__(16) float As[64][68];   // As[k][m]
    __shared__ __align__(16) float Bs[64][68];   // Bs[k][j]

    int by = blockIdx.y;
    const float* W; const float* bias; float* out; int ldw, ldo, colbase;
    if (by < 4)       { W = Wq; bias = bq; out = g_q;  ldw = HC;  ldo = HC;  colbase = by * 64; }
    else if (by < 8)  { W = Wk; bias = bk; out = g_k;  ldw = HC;  ldo = HC;  colbase = (by - 4) * 64; }
    else if (by < 12) { W = Wv; bias = bv; out = g_v;  ldw = HC;  ldo = HC;  colbase = (by - 8) * 64; }
    else              { W = Ws; bias = bs; out = g_xr; ldw = DDIM; ldo = DDIM; colbase = 0; }

    int row0 = blockIdx.x * 64;
    int tid  = threadIdx.x;

    // load A (gathered emb rows), transposed into As[k][m]
    {
        int r = tid >> 2, qtr = tid & 3;
        int gr = row0 + r;
        if (gr < N_NODES) {
            const float4* src = (const float4*)(emb + x[gr] * DDIM + qtr * 16);
            #pragma unroll
            for (int u = 0; u < 4; u++) {
                float4 v = src[u];
                int k0 = qtr * 16 + u * 4;
                As[k0 + 0][r] = v.x; As[k0 + 1][r] = v.y;
                As[k0 + 2][r] = v.z; As[k0 + 3][r] = v.w;
            }
        } else {
            #pragma unroll
            for (int u = 0; u < 4; u++) {
                int k0 = qtr * 16 + u * 4;
                As[k0 + 0][r] = 0.f; As[k0 + 1][r] = 0.f;
                As[k0 + 2][r] = 0.f; As[k0 + 3][r] = 0.f;
            }
        }
    }
    // load B tile: Bs[k][j]
    {
        int k = tid >> 2, qtr = tid & 3;
        const float4* src = (const float4*)(W + k * ldw + colbase + qtr * 16);
        #pragma unroll
        for (int u = 0; u < 4; u++) {
            *(float4*)&Bs[k][qtr * 16 + u * 4] = src[u];
        }
    }
    __syncthreads();

    int tx = tid & 15, ty = tid >> 4;
    int m0 = ty * 4, j0 = tx * 4;
    float acc[4][4];
    #pragma unroll
    for (int i = 0; i < 4; i++)
        #pragma unroll
        for (int j = 0; j < 4; j++) acc[i][j] = 0.f;

    #pragma unroll
    for (int k = 0; k < 64; k++) {
        float4 a = *(const float4*)&As[k][m0];
        float4 b = *(const float4*)&Bs[k][j0];
        float av[4] = {a.x, a.y, a.z, a.w};
        float bv4[4] = {b.x, b.y, b.z, b.w};
        #pragma unroll
        for (int i = 0; i < 4; i++)
            #pragma unroll
            for (int j = 0; j < 4; j++)
                acc[i][j] = fmaf(av[i], bv4[j], acc[i][j]);
    }

    float4 bvec = *(const float4*)&bias[colbase + j0];
    #pragma unroll
    for (int i = 0; i < 4; i++) {
        int gr = row0 + m0 + i;
        if (gr < N_NODES) {
            float4 o;
            o.x = acc[i][0] + bvec.x; o.y = acc[i][1] + bvec.y;
            o.z = acc[i][2] + bvec.z; o.w = acc[i][3] + bvec.w;
            *(float4*)&out[gr * ldo + colbase + j0] = o;
        }
    }
}

// ---------------- fused attention aggregate + skip gate (warp per node) ----
__global__ void aggregate_kernel(const float* __restrict__ Wbeta) {
    int gw = (blockIdx.x * blockDim.x + threadIdx.x) >> 5;
    if (gw >= N_NODES) return;
    int node = gw;
    if (!g_flag[node]) return;   // only task-reachable nodes need h_final

    int lane = threadIdx.x & 31;
    int cg   = lane & 7;         // lane = head*8 + cg; lane handles channels cg*8..cg*8+7

    const float4* qp = (const float4*)(g_q + node * HC + lane * 8);
    float4 q0 = qp[0], q1 = qp[1];

    float a0=0,a1=0,a2=0,a3=0,a4=0,a5=0,a6=0,a7=0;
    float den = 0.f;
    int s = g_start[node];
    int d = g_deg[node];
    for (int e = 0; e < d; e++) {
        int src = g_adj[s + e];
        const float4* kp = (const float4*)(g_k + src * HC + lane * 8);
        float4 k0 = kp[0], k1 = kp[1];
        float dot = q0.x*k0.x + q0.y*k0.y + q0.z*k0.z + q0.w*k0.w
                  + q1.x*k1.x + q1.y*k1.y + q1.z*k1.z + q1.w*k1.w;
        dot += __shfl_xor_sync(0xffffffffu, dot, 1);
        dot += __shfl_xor_sync(0xffffffffu, dot, 2);
        dot += __shfl_xor_sync(0xffffffffu, dot, 4);
        // alpha magnitudes are ~1e-2 here, so softmax without max-shift is exact
        float ex = __expf(dot * 0.125f);
        den += ex;
        const float4* vp = (const float4*)(g_v + src * HC + lane * 8);
        float4 v0 = vp[0], v1 = vp[1];
        a0 += ex * v0.x; a1 += ex * v0.y; a2 += ex * v0.z; a3 += ex * v0.w;
        a4 += ex * v1.x; a5 += ex * v1.y; a6 += ex * v1.z; a7 += ex * v1.w;
    }
    float invden = (den > 0.f) ? (1.f / den) : 0.f;
    float o[8] = {a0*invden, a1*invden, a2*invden, a3*invden,
                  a4*invden, a5*invden, a6*invden, a7*invden};
    // mean over heads: sum across the 4 head-groups (xor 8, 16), /4
    #pragma unroll
    for (int j = 0; j < 8; j++) {
        float t = o[j];
        t += __shfl_xor_sync(0xffffffffu, t, 8);
        t += __shfl_xor_sync(0xffffffffu, t, 16);
        o[j] = t * 0.25f;
    }
    // skip branch
    const float4* xp = (const float4*)(g_xr + node * DDIM + cg * 8);
    float4 x0 = xp[0], x1 = xp[1];
    float xr[8] = {x0.x, x0.y, x0.z, x0.w, x1.x, x1.y, x1.z, x1.w};

    float part = 0.f;
    #pragma unroll
    for (int j = 0; j < 8; j++) {
        int c = cg * 8 + j;
        part += o[j] * Wbeta[c] + xr[j] * Wbeta[64 + c] + (o[j] - xr[j]) * Wbeta[128 + c];
    }
    part += __shfl_xor_sync(0xffffffffu, part, 1);
    part += __shfl_xor_sync(0xffffffffu, part, 2);
    part += __shfl_xor_sync(0xffffffffu, part, 4);
    float beta = 1.f / (1.f + __expf(-part));

    float hf[8];
    #pragma unroll
    for (int j = 0; j < 8; j++) hf[j] = beta * xr[j] + (1.f - beta) * o[j];

    if (lane < 8) {
        float4 w0 = make_float4(hf[0], hf[1], hf[2], hf[3]);
        float4 w1 = make_float4(hf[4], hf[5], hf[6], hf[7]);
        *(float4*)&g_hf[node * DDIM + cg * 8]     = w0;
        *(float4*)&g_hf[node * DDIM + cg * 8 + 4] = w1;
    }
}

// ---------------- final MLP head (warp per task) ----------------
__global__ void mlp_kernel(const int* __restrict__ task,
                           const float* __restrict__ W1, const float* __restrict__ b1,
                           const float* __restrict__ W2, const float* __restrict__ b2,
                           float* __restrict__ out) {
    __shared__ float W1s[64 * 32];
    __shared__ float W2s[32];
    __shared__ float b1s[32];
    int tid = threadIdx.x;
    for (int i = tid; i < 64 * 32; i += 128) W1s[i] = W1[i];
    if (tid < 32) { W2s[tid] = W2[tid]; b1s[tid] = b1[tid]; }
    __syncthreads();

    int warp = tid >> 5, lane = tid & 31;
    int t = blockIdx.x * 4 + warp;
    if (t >= N_TASK) return;
    int node = task[t];
    float hv0 = g_hf[node * DDIM + lane];
    float hv1 = g_hf[node * DDIM + 32 + lane];
    float acc = b1s[lane];
    #pragma unroll
    for (int c = 0; c < 32; c++)
        acc = fmaf(__shfl_sync(0xffffffffu, hv0, c), W1s[c * 32 + lane], acc);
    #pragma unroll
    for (int c = 0; c < 32; c++)
        acc = fmaf(__shfl_sync(0xffffffffu, hv1, c), W1s[(32 + c) * 32 + lane], acc);
    float hid = fmaxf(acc, 0.f);
    float p = hid * W2s[lane];
    p += __shfl_xor_sync(0xffffffffu, p, 16);
    p += __shfl_xor_sync(0xffffffffu, p, 8);
    p += __shfl_xor_sync(0xffffffffu, p, 4);
    p += __shfl_xor_sync(0xffffffffu, p, 2);
    p += __shfl_xor_sync(0xffffffffu, p, 1);
    if (lane == 0) out[t] = 1.f / (1.f + __expf(-(p + b2[0])));
}

// ---------------- launch ----------------
extern "C" void kernel_launch(void* const* d_in, const int* in_sizes, int n_in,
                              void* d_out, int out_size) {
    const int*   x     = (const int*)  d_in[0];
    const int*   ei    = (const int*)  d_in[1];
    const int*   task  = (const int*)  d_in[2];
    const float* emb   = (const float*)d_in[3];
    const float* Wq    = (const float*)d_in[4];
    const float* bq    = (const float*)d_in[5];
    const float* Wk    = (const float*)d_in[6];
    const float* bk    = (const float*)d_in[7];
    const float* Wv    = (const float*)d_in[8];
    const float* bv    = (const float*)d_in[9];
    const float* Ws    = (const float*)d_in[10];
    const float* bs    = (const float*)d_in[11];
    const float* Wbeta = (const float*)d_in[12];
    const float* W1    = (const float*)d_in[13];
    const float* b1    = (const float*)d_in[14];
    const float* W2    = (const float*)d_in[15];
    const float* b2    = (const float*)d_in[16];
    float* out = (float*)d_out;

    const int* src = ei;            // edge_index[0]
    const int* dst = ei + N_EDGES;  // edge_index[1]

    zero_kernel  <<<(N_NODES + 255) / 256, 256>>>();
    flag_kernel  <<<(N_TASK  + 255) / 256, 256>>>(task);
    degree_kernel<<<(N_EDGES + 255) / 256, 256>>>(dst);
    scan_kernel  <<<1, 1024>>>();
    scatter_kernel<<<(N_EDGES + 255) / 256, 256>>>(src, dst);

    dim3 gg((N_NODES + 63) / 64, 13);
    gemm_kernel<<<gg, 256>>>(x, emb, Wq, bq, Wk, bk, Wv, bv, Ws, bs);

    aggregate_kernel<<<(N_NODES * 32 + 255) / 256, 256>>>(Wbeta);
    mlp_kernel<<<(N_TASK + 3) / 4, 128>>>(task, W1, b1, W2, b2, out);
}

// round 4
// speedup vs baseline: 2.2660x; 2.2660x over previous
#include <cuda_runtime.h>

#define N_NODES 50000
#define N_EDGES 200000
#define N_TASK  10000
#define DDIM    64
#define HC      256   // H*C = 4*64
#define MAXQ    N_TASK     // flagged nodes <= N_TASK
#define MAXKV   N_NODES    // needed src nodes <= N_NODES

// ---------------- scratch (device globals; no allocations) ----------------
__device__ __align__(16) float g_q [MAXQ  * HC];     // compacted by qslot
__device__ __align__(16) float g_xr[MAXQ  * DDIM];
__device__ __align__(16) float g_hf[MAXQ  * DDIM];
__device__ __align__(16) float g_k [MAXKV * HC];     // compacted by kvslot
__device__ __align__(16) float g_v [MAXKV * HC];
__device__ int g_flag   [N_NODES];
__device__ int g_srcneed[N_NODES];
__device__ int g_deg    [N_NODES];
__device__ int g_start  [N_NODES];
__device__ int g_cursor [N_NODES];
__device__ int g_qslot  [N_NODES];
__device__ int g_kvslot [N_NODES];
__device__ int g_qlist  [MAXQ];
__device__ int g_kvlist [MAXKV];
__device__ int g_adj    [N_EDGES];
__device__ int g_total_adj, g_cnt_q, g_cnt_kv;

// ---------------- setup kernels ----------------
__global__ void zero_kernel() {
    int i = blockIdx.x * blockDim.x + threadIdx.x;
    if (i < N_NODES) { g_flag[i] = 0; g_srcneed[i] = 0; g_deg[i] = 0; }
    if (i == 0) { g_total_adj = 0; g_cnt_q = 0; g_cnt_kv = 0; }
}

__global__ void flag_kernel(const int* __restrict__ task) {
    int t = blockIdx.x * blockDim.x + threadIdx.x;
    if (t < N_TASK) g_flag[task[t]] = 1;
}

// per flagged edge: count degree of dst, mark src as kv-needed
__global__ void mark_kernel(const int* __restrict__ srcArr,
                            const int* __restrict__ dstArr) {
    int e = blockIdx.x * blockDim.x + threadIdx.x;
    if (e < N_EDGES) {
        int dn = dstArr[e];
        if (g_flag[dn]) {
            atomicAdd(&g_deg[dn], 1);
            g_srcneed[srcArr[e]] = 1;
        }
    }
}

// warp-aggregated allocator: adjacency ranges + compacted q/kv slot lists.
// Bucket ORDER is irrelevant (only disjoint contiguity matters), so a plain
// atomic bump allocator replaces the 50us serial scan.
__global__ void alloc_kernel() {
    int i = blockIdx.x * blockDim.x + threadIdx.x;
    int lane = threadIdx.x & 31;
    unsigned full = 0xffffffffu;
    bool inb = (i < N_NODES);
    bool fl  = inb && g_flag[i];
    bool sn  = inb && g_srcneed[i];
    int deg  = fl ? g_deg[i] : 0;

    // adjacency range: warp inclusive scan of deg, one atomic per warp
    int incl = deg;
    #pragma unroll
    for (int o = 1; o < 32; o <<= 1) {
        int y = __shfl_up_sync(full, incl, o);
        if (lane >= o) incl += y;
    }
    int wsum = __shfl_sync(full, incl, 31);
    int base = 0;
    if (lane == 0 && wsum > 0) base = atomicAdd(&g_total_adj, wsum);
    base = __shfl_sync(full, base, 0);
    if (fl) {
        int st = base + incl - deg;
        g_start[i] = st;
        g_cursor[i] = st;
    }
    // q slots
    unsigned bmq = __ballot_sync(full, fl);
    int qb = 0;
    if (lane == 0 && bmq) qb = atomicAdd(&g_cnt_q, __popc(bmq));
    qb = __shfl_sync(full, qb, 0);
    if (fl) {
        int slot = qb + __popc(bmq & ((1u << lane) - 1u));
        g_qslot[i] = slot;
        g_qlist[slot] = i;
    }
    // kv slots
    unsigned bmk = __ballot_sync(full, sn);
    int kb = 0;
    if (lane == 0 && bmk) kb = atomicAdd(&g_cnt_kv, __popc(bmk));
    kb = __shfl_sync(full, kb, 0);
    if (sn) {
        int slot = kb + __popc(bmk & ((1u << lane) - 1u));
        g_kvslot[i] = slot;
        g_kvlist[slot] = i;
    }
}

__global__ void scatter_kernel(const int* __restrict__ srcArr,
                               const int* __restrict__ dstArr) {
    int e = blockIdx.x * blockDim.x + threadIdx.x;
    if (e < N_EDGES) {
        int dn = dstArr[e];
        if (g_flag[dn]) {
            int p = atomicAdd(&g_cursor[dn], 1);
            g_adj[p] = g_kvslot[srcArr[e]];  // store kv-slot directly
        }
    }
}

// ---------------- compacted embed-gather GEMM core ----------------
// rows from list (gathered emb), 64x64 tile, K=64.
__device__ __forceinline__ void gemm_tile(
    const int* __restrict__ list, int cnt,
    const int* __restrict__ x, const float* __restrict__ emb,
    const float* __restrict__ W, const float* __restrict__ bias,
    float* __restrict__ out, int ldw, int ldo, int colbase)
{
    __shared__ __align__(16) float As[64][68];
    __shared__ __align__(16) float Bs[64][68];
    int row0 = blockIdx.x * 64;
    int tid  = threadIdx.x;

    {
        int r = tid >> 2, qtr = tid & 3;
        int gr = row0 + r;
        if (gr < cnt) {
            const float4* srcp = (const float4*)(emb + x[list[gr]] * DDIM + qtr * 16);
            #pragma unroll
            for (int u = 0; u < 4; u++) {
                float4 v = srcp[u];
                int k0 = qtr * 16 + u * 4;
                As[k0 + 0][r] = v.x; As[k0 + 1][r] = v.y;
                As[k0 + 2][r] = v.z; As[k0 + 3][r] = v.w;
            }
        } else {
            #pragma unroll
            for (int u = 0; u < 4; u++) {
                int k0 = qtr * 16 + u * 4;
                As[k0 + 0][r] = 0.f; As[k0 + 1][r] = 0.f;
                As[k0 + 2][r] = 0.f; As[k0 + 3][r] = 0.f;
            }
        }
    }
    {
        int k = tid >> 2, qtr = tid & 3;
        const float4* srcp = (const float4*)(W + k * ldw + colbase + qtr * 16);
        #pragma unroll
        for (int u = 0; u < 4; u++)
            *(float4*)&Bs[k][qtr * 16 + u * 4] = srcp[u];
    }
    __syncthreads();

    int tx = tid & 15, ty = tid >> 4;
    int m0 = ty * 4, j0 = tx * 4;
    float acc[4][4];
    #pragma unroll
    for (int i = 0; i < 4; i++)
        #pragma unroll
        for (int j = 0; j < 4; j++) acc[i][j] = 0.f;

    #pragma unroll
    for (int k = 0; k < 64; k++) {
        float4 a = *(const float4*)&As[k][m0];
        float4 b = *(const float4*)&Bs[k][j0];
        float av[4]  = {a.x, a.y, a.z, a.w};
        float bv4[4] = {b.x, b.y, b.z, b.w};
        #pragma unroll
        for (int i = 0; i < 4; i++)
            #pragma unroll
            for (int j = 0; j < 4; j++)
                acc[i][j] = fmaf(av[i], bv4[j], acc[i][j]);
    }

    float4 bvec = *(const float4*)&bias[colbase + j0];
    #pragma unroll
    for (int i = 0; i < 4; i++) {
        int gr = row0 + m0 + i;
        if (gr < cnt) {
            float4 o;
            o.x = acc[i][0] + bvec.x; o.y = acc[i][1] + bvec.y;
            o.z = acc[i][2] + bvec.z; o.w = acc[i][3] + bvec.w;
            *(float4*)&out[gr * ldo + colbase + j0] = o;
        }
    }
}

// q (4 col-tiles) + xr (1 tile) over flagged nodes
__global__ __launch_bounds__(256) void gemm_q_kernel(
    const int* __restrict__ x, const float* __restrict__ emb,
    const float* __restrict__ Wq, const float* __restrict__ bq,
    const float* __restrict__ Ws, const float* __restrict__ bs)
{
    int cnt = g_cnt_q;
    if ((int)(blockIdx.x * 64) >= cnt) return;
    int by = blockIdx.y;
    if (by < 4) gemm_tile(g_qlist, cnt, x, emb, Wq, bq, g_q,  HC,   HC,   by * 64);
    else        gemm_tile(g_qlist, cnt, x, emb, Ws, bs, g_xr, DDIM, DDIM, 0);
}

// k (4 tiles) + v (4 tiles) over needed src nodes
__global__ __launch_bounds__(256) void gemm_kv_kernel(
    const int* __restrict__ x, const float* __restrict__ emb,
    const float* __restrict__ Wk, const float* __restrict__ bk,
    const float* __restrict__ Wv, const float* __restrict__ bv)
{
    int cnt = g_cnt_kv;
    if ((int)(blockIdx.x * 64) >= cnt) return;
    int by = blockIdx.y;
    if (by < 4) gemm_tile(g_kvlist, cnt, x, emb, Wk, bk, g_k, HC, HC, by * 64);
    else        gemm_tile(g_kvlist, cnt, x, emb, Wv, bv, g_v, HC, HC, (by - 4) * 64);
}

// ---------------- fused attention aggregate + skip gate (warp per qslot) ----
__global__ void aggregate_kernel(const float* __restrict__ Wbeta) {
    int qslot = (blockIdx.x * blockDim.x + threadIdx.x) >> 5;
    if (qslot >= g_cnt_q) return;
    int node = g_qlist[qslot];

    int lane = threadIdx.x & 31;
    int cg   = lane & 7;

    const float4* qp = (const float4*)(g_q + qslot * HC + lane * 8);
    float4 q0 = qp[0], q1 = qp[1];

    float a0=0,a1=0,a2=0,a3=0,a4=0,a5=0,a6=0,a7=0;
    float den = 0.f;
    int s = g_start[node];
    int d = g_deg[node];
    for (int e = 0; e < d; e++) {
        int kvslot = g_adj[s + e];
        const float4* kp = (const float4*)(g_k + kvslot * HC + lane * 8);
        float4 k0 = kp[0], k1 = kp[1];
        const float4* vp = (const float4*)(g_v + kvslot * HC + lane * 8);
        float4 v0 = vp[0], v1 = vp[1];
        float dot = q0.x*k0.x + q0.y*k0.y + q0.z*k0.z + q0.w*k0.w
                  + q1.x*k1.x + q1.y*k1.y + q1.z*k1.z + q1.w*k1.w;
        dot += __shfl_xor_sync(0xffffffffu, dot, 1);
        dot += __shfl_xor_sync(0xffffffffu, dot, 2);
        dot += __shfl_xor_sync(0xffffffffu, dot, 4);
        // |alpha| ~ 1e-2 here, so softmax without max-shift is exact
        float ex = __expf(dot * 0.125f);
        den += ex;
        a0 += ex * v0.x; a1 += ex * v0.y; a2 += ex * v0.z; a3 += ex * v0.w;
        a4 += ex * v1.x; a5 += ex * v1.y; a6 += ex * v1.z; a7 += ex * v1.w;
    }
    float invden = (den > 0.f) ? (1.f / den) : 0.f;
    float o[8] = {a0*invden, a1*invden, a2*invden, a3*invden,
                  a4*invden, a5*invden, a6*invden, a7*invden};
    #pragma unroll
    for (int j = 0; j < 8; j++) {
        float t = o[j];
        t += __shfl_xor_sync(0xffffffffu, t, 8);
        t += __shfl_xor_sync(0xffffffffu, t, 16);
        o[j] = t * 0.25f;   // mean over 4 heads
    }
    const float4* xp = (const float4*)(g_xr + qslot * DDIM + cg * 8);
    float4 x0 = xp[0], x1 = xp[1];
    float xr[8] = {x0.x, x0.y, x0.z, x0.w, x1.x, x1.y, x1.z, x1.w};

    float part = 0.f;
    #pragma unroll
    for (int j = 0; j < 8; j++) {
        int c = cg * 8 + j;
        part += o[j] * Wbeta[c] + xr[j] * Wbeta[64 + c] + (o[j] - xr[j]) * Wbeta[128 + c];
    }
    part += __shfl_xor_sync(0xffffffffu, part, 1);
    part += __shfl_xor_sync(0xffffffffu, part, 2);
    part += __shfl_xor_sync(0xffffffffu, part, 4);
    float beta = 1.f / (1.f + __expf(-part));

    float hf[8];
    #pragma unroll
    for (int j = 0; j < 8; j++) hf[j] = beta * xr[j] + (1.f - beta) * o[j];

    if (lane < 8) {
        *(float4*)&g_hf[qslot * DDIM + cg * 8]     = make_float4(hf[0], hf[1], hf[2], hf[3]);
        *(float4*)&g_hf[qslot * DDIM + cg * 8 + 4] = make_float4(hf[4], hf[5], hf[6], hf[7]);
    }
}

// ---------------- final MLP head (warp per task) ----------------
__global__ void mlp_kernel(const int* __restrict__ task,
                           const float* __restrict__ W1, const float* __restrict__ b1,
                           const float* __restrict__ W2, const float* __restrict__ b2,
                           float* __restrict__ out) {
    __shared__ float W1s[64 * 32];
    __shared__ float W2s[32];
    __shared__ float b1s[32];
    int tid = threadIdx.x;
    for (int i = tid; i < 64 * 32; i += 128) W1s[i] = W1[i];
    if (tid < 32) { W2s[tid] = W2[tid]; b1s[tid] = b1[tid]; }
    __syncthreads();

    int warp = tid >> 5, lane = tid & 31;
    int t = blockIdx.x * 4 + warp;
    if (t >= N_TASK) return;
    int qslot = g_qslot[task[t]];
    float hv0 = g_hf[qslot * DDIM + lane];
    float hv1 = g_hf[qslot * DDIM + 32 + lane];
    float acc = b1s[lane];
    #pragma unroll
    for (int c = 0; c < 32; c++)
        acc = fmaf(__shfl_sync(0xffffffffu, hv0, c), W1s[c * 32 + lane], acc);
    #pragma unroll
    for (int c = 0; c < 32; c++)
        acc = fmaf(__shfl_sync(0xffffffffu, hv1, c), W1s[(32 + c) * 32 + lane], acc);
    float hid = fmaxf(acc, 0.f);
    float p = hid * W2s[lane];
    p += __shfl_xor_sync(0xffffffffu, p, 16);
    p += __shfl_xor_sync(0xffffffffu, p, 8);
    p += __shfl_xor_sync(0xffffffffu, p, 4);
    p += __shfl_xor_sync(0xffffffffu, p, 2);
    p += __shfl_xor_sync(0xffffffffu, p, 1);
    if (lane == 0) out[t] = 1.f / (1.f + __expf(-(p + b2[0])));
}

// ---------------- launch ----------------
extern "C" void kernel_launch(void* const* d_in, const int* in_sizes, int n_in,
                              void* d_out, int out_size) {
    const int*   x     = (const int*)  d_in[0];
    const int*   ei    = (const int*)  d_in[1];
    const int*   task  = (const int*)  d_in[2];
    const float* emb   = (const float*)d_in[3];
    const float* Wq    = (const float*)d_in[4];
    const float* bq    = (const float*)d_in[5];
    const float* Wk    = (const float*)d_in[6];
    const float* bk    = (const float*)d_in[7];
    const float* Wv    = (const float*)d_in[8];
    const float* bv    = (const float*)d_in[9];
    const float* Ws    = (const float*)d_in[10];
    const float* bs    = (const float*)d_in[11];
    const float* Wbeta = (const float*)d_in[12];
    const float* W1    = (const float*)d_in[13];
    const float* b1    = (const float*)d_in[14];
    const float* W2    = (const float*)d_in[15];
    const float* b2    = (const float*)d_in[16];
    float* out = (float*)d_out;

    const int* src = ei;            // edge_index[0]
    const int* dst = ei + N_EDGES;  // edge_index[1]

    zero_kernel   <<<(N_NODES + 255) / 256, 256>>>();
    flag_kernel   <<<(N_TASK  + 255) / 256, 256>>>(task);
    mark_kernel   <<<(N_EDGES + 255) / 256, 256>>>(src, dst);
    alloc_kernel  <<<(N_NODES + 255) / 256, 256>>>();
    scatter_kernel<<<(N_EDGES + 255) / 256, 256>>>(src, dst);

    dim3 gq((MAXQ + 63) / 64, 5);
    gemm_q_kernel<<<gq, 256>>>(x, emb, Wq, bq, Ws, bs);
    dim3 gkv((MAXKV + 63) / 64, 8);
    gemm_kv_kernel<<<gkv, 256>>>(x, emb, Wk, bk, Wv, bv);

    aggregate_kernel<<<(MAXQ * 32 + 255) / 256, 256>>>(Wbeta);
    mlp_kernel<<<(N_TASK + 3) / 4, 128>>>(task, W1, b1, W2, b2, out);
}

// round 6
// speedup vs baseline: 2.3836x; 1.0519x over previous
#include <cuda_runtime.h>

#define N_NODES 50000
#define N_EDGES 200000
#define N_TASK  10000
#define DDIM    64
#define HC      256   // H*C = 4*64
#define MAXQ    N_TASK
#define MAXKV   N_NODES

// ---------------- scratch (device globals; no allocations) ----------------
__device__ __align__(16) float g_q [MAXQ  * HC];     // compacted by qslot
__device__ __align__(16) float g_xr[MAXQ  * DDIM];
__device__ __align__(16) float g_hf[MAXQ  * DDIM];
__device__ __align__(16) float g_k [MAXKV * HC];     // compacted by kvslot
__device__ __align__(16) float g_v [MAXKV * HC];
__device__ int g_flag   [N_NODES];
__device__ int g_srcneed[N_NODES];
__device__ int g_deg    [N_NODES];
__device__ int g_start  [N_NODES];
__device__ int g_cursor [N_NODES];
__device__ int g_qslot  [N_NODES];
__device__ int g_kvslot [N_NODES];
__device__ int g_qlist  [MAXQ];
__device__ int g_kvlist [MAXKV];
__device__ int g_adj    [N_EDGES];
__device__ int g_total_adj, g_cnt_q, g_cnt_kv;

// ---------------- setup kernels ----------------
__global__ void zero_kernel() {
    int i = blockIdx.x * blockDim.x + threadIdx.x;
    if (i < N_NODES) { g_flag[i] = 0; g_srcneed[i] = 0; g_deg[i] = 0; }
    if (i == 0) { g_total_adj = 0; g_cnt_q = 0; g_cnt_kv = 0; }
}

__global__ void flag_kernel(const int* __restrict__ task) {
    int t = blockIdx.x * blockDim.x + threadIdx.x;
    if (t < N_TASK) g_flag[task[t]] = 1;
}

__global__ void mark_kernel(const int* __restrict__ srcArr,
                            const int* __restrict__ dstArr) {
    int e = blockIdx.x * blockDim.x + threadIdx.x;
    if (e < N_EDGES) {
        int dn = dstArr[e];
        if (g_flag[dn]) {
            atomicAdd(&g_deg[dn], 1);
            g_srcneed[srcArr[e]] = 1;
        }
    }
}

// warp-aggregated bump allocator: adjacency ranges + compacted slot lists.
__global__ void alloc_kernel() {
    int i = blockIdx.x * blockDim.x + threadIdx.x;
    int lane = threadIdx.x & 31;
    unsigned full = 0xffffffffu;
    bool inb = (i < N_NODES);
    bool fl  = inb && g_flag[i];
    bool sn  = inb && g_srcneed[i];
    int deg  = fl ? g_deg[i] : 0;

    int incl = deg;
    #pragma unroll
    for (int o = 1; o < 32; o <<= 1) {
        int y = __shfl_up_sync(full, incl, o);
        if (lane >= o) incl += y;
    }
    int wsum = __shfl_sync(full, incl, 31);
    int base = 0;
    if (lane == 0 && wsum > 0) base = atomicAdd(&g_total_adj, wsum);
    base = __shfl_sync(full, base, 0);
    if (fl) {
        int st = base + incl - deg;
        g_start[i] = st;
        g_cursor[i] = st;
    }
    unsigned bmq = __ballot_sync(full, fl);
    int qb = 0;
    if (lane == 0 && bmq) qb = atomicAdd(&g_cnt_q, __popc(bmq));
    qb = __shfl_sync(full, qb, 0);
    if (fl) {
        int slot = qb + __popc(bmq & ((1u << lane) - 1u));
        g_qslot[i] = slot;
        g_qlist[slot] = i;
    }
    unsigned bmk = __ballot_sync(full, sn);
    int kb = 0;
    if (lane == 0 && bmk) kb = atomicAdd(&g_cnt_kv, __popc(bmk));
    kb = __shfl_sync(full, kb, 0);
    if (sn) {
        int slot = kb + __popc(bmk & ((1u << lane) - 1u));
        g_kvslot[i] = slot;
        g_kvlist[slot] = i;
    }
}

__global__ void scatter_kernel(const int* __restrict__ srcArr,
                               const int* __restrict__ dstArr) {
    int e = blockIdx.x * blockDim.x + threadIdx.x;
    if (e < N_EDGES) {
        int dn = dstArr[e];
        if (g_flag[dn]) {
            int p = atomicAdd(&g_cursor[dn], 1);
            g_adj[p] = g_kvslot[srcArr[e]];
        }
    }
}

// ---------------- tf32 tensor-core GEMM helpers ----------------
__device__ __forceinline__ unsigned f2tf32(float f) {
    unsigned r;
    asm("cvt.rna.tf32.f32 %0, %1;" : "=r"(r) : "f"(f));
    return r;
}

__device__ __forceinline__ void mma_tf32(float c[4],
                                         unsigned a0, unsigned a1, unsigned a2, unsigned a3,
                                         unsigned b0, unsigned b1) {
    asm volatile(
        "mma.sync.aligned.m16n8k8.row.col.f32.tf32.tf32.f32 "
        "{%0,%1,%2,%3}, {%4,%5,%6,%7}, {%8,%9}, {%0,%1,%2,%3};"
        : "+f"(c[0]), "+f"(c[1]), "+f"(c[2]), "+f"(c[3])
        : "r"(a0), "r"(a1), "r"(a2), "r"(a3), "r"(b0), "r"(b1));
}

// Merged gathered GEMM: out[r][col] = emb[x[list[r]]] . W[:,col] + bias.
// blockIdx.y: 0-3 -> q tiles, 4 -> xr, 5-8 -> k tiles, 9-12 -> v tiles.
// 128 threads, block tile 64(M) x 64(N) x 64(K), tf32 mma.sync.
__global__ __launch_bounds__(128) void gemm_tc_kernel(
    const int*   __restrict__ x,  const float* __restrict__ emb,
    const float* __restrict__ Wq, const float* __restrict__ bq,
    const float* __restrict__ Wk, const float* __restrict__ bk,
    const float* __restrict__ Wv, const float* __restrict__ bv,
    const float* __restrict__ Ws, const float* __restrict__ bs)
{
    __shared__ __align__(16) unsigned As[64 * 68];
    __shared__ __align__(16) unsigned Bs[64 * 68];

    int by = blockIdx.y;
    const int* list; int cnt;
    if (by < 5) { list = g_qlist;  cnt = g_cnt_q;  }
    else        { list = g_kvlist; cnt = g_cnt_kv; }
    int row0 = blockIdx.x * 64;
    if (row0 >= cnt) return;

    const float* W; const float* bias; float* out; int ldw, ldo, colbase;
    if (by < 4)       { W = Wq; bias = bq; out = g_q;  ldw = HC;   ldo = HC;   colbase = by * 64; }
    else if (by == 4) { W = Ws; bias = bs; out = g_xr; ldw = DDIM; ldo = DDIM; colbase = 0; }
    else if (by < 9)  { W = Wk; bias = bk; out = g_k;  ldw = HC;   ldo = HC;   colbase = (by - 5) * 64; }
    else              { W = Wv; bias = bv; out = g_v;  ldw = HC;   ldo = HC;   colbase = (by - 9) * 64; }

    int tid = threadIdx.x;
    // ---- load A: gathered emb rows, tf32-converted. 2 threads per row. ----
    {
        int r = tid >> 1, h = tid & 1;
        int gr = row0 + r;
        unsigned* dstp = &As[r * 68 + h * 32];
        if (gr < cnt) {
            const float4* srcp = (const float4*)(emb + x[list[gr]] * DDIM + h * 32);
            #pragma unroll
            for (int u = 0; u < 8; u++) {
                float4 v = srcp[u];
                uint4 o;
                o.x = f2tf32(v.x); o.y = f2tf32(v.y);
                o.z = f2tf32(v.z); o.w = f2tf32(v.w);
                *(uint4*)&dstp[u * 4] = o;
            }
        } else {
            uint4 z = make_uint4(0, 0, 0, 0);
            #pragma unroll
            for (int u = 0; u < 8; u++) *(uint4*)&dstp[u * 4] = z;
        }
    }
    // ---- load B: W[k][colbase + 0..63], tf32-converted. ----
    {
        int k = tid >> 1, h = tid & 1;
        const float4* srcp = (const float4*)(W + k * ldw + colbase + h * 32);
        unsigned* dstp = &Bs[k * 68 + h * 32];
        #pragma unroll
        for (int u = 0; u < 8; u++) {
            float4 v = srcp[u];
            uint4 o;
            o.x = f2tf32(v.x); o.y = f2tf32(v.y);
            o.z = f2tf32(v.z); o.w = f2tf32(v.w);
            *(uint4*)&dstp[u * 4] = o;
        }
    }
    __syncthreads();

    int lane = tid & 31, w = tid >> 5;
    int g = lane >> 2, t = lane & 3;
    int mb = w * 16;            // warp's 16-row slice

    float acc[8][4];
    #pragma unroll
    for (int j = 0; j < 8; j++)
        #pragma unroll
        for (int c = 0; c < 4; c++) acc[j][c] = 0.f;

    #pragma unroll
    for (int ks = 0; ks < 8; ks++) {
        int k0 = ks * 8;
        unsigned a0 = As[(mb + g)     * 68 + k0 + t];
        unsigned a1 = As[(mb + g + 8) * 68 + k0 + t];
        unsigned a2 = As[(mb + g)     * 68 + k0 + t + 4];
        unsigned a3 = As[(mb + g + 8) * 68 + k0 + t + 4];
        #pragma unroll
        for (int j = 0; j < 8; j++) {
            unsigned b0 = Bs[(k0 + t)     * 68 + j * 8 + g];
            unsigned b1 = Bs[(k0 + t + 4) * 68 + j * 8 + g];
            mma_tf32(acc[j], a0, a1, a2, a3, b0, b1);
        }
    }

    // ---- epilogue: +bias, guarded float2 stores ----
    int gr0 = row0 + mb + g;
    int gr1 = gr0 + 8;
    #pragma unroll
    for (int j = 0; j < 8; j++) {
        int n = colbase + j * 8 + t * 2;
        float bx = bias[n], byv = bias[n + 1];
        if (gr0 < cnt) {
            float2 o0 = make_float2(acc[j][0] + bx, acc[j][1] + byv);
            *(float2*)&out[gr0 * ldo + n] = o0;
        }
        if (gr1 < cnt) {
            float2 o1 = make_float2(acc[j][2] + bx, acc[j][3] + byv);
            *(float2*)&out[gr1 * ldo + n] = o1;
        }
    }
}

// ---------------- fused attention aggregate + skip gate (warp per qslot) ----
__global__ void aggregate_kernel(const float* __restrict__ Wbeta) {
    int qslot = (blockIdx.x * blockDim.x + threadIdx.x) >> 5;
    if (qslot >= g_cnt_q) return;
    int node = g_qlist[qslot];

    int lane = threadIdx.x & 31;
    int cg   = lane & 7;

    const float4* qp = (const float4*)(g_q + qslot * HC + lane * 8);
    float4 q0 = qp[0], q1 = qp[1];

    float a0=0,a1=0,a2=0,a3=0,a4=0,a5=0,a6=0,a7=0;
    float den = 0.f;
    int s = g_start[node];
    int d = g_deg[node];
    for (int e = 0; e < d; e++) {
        int kvslot = g_adj[s + e];
        const float4* kp = (const float4*)(g_k + kvslot * HC + lane * 8);
        float4 k0 = kp[0], k1 = kp[1];
        const float4* vp = (const float4*)(g_v + kvslot * HC + lane * 8);
        float4 v0 = vp[0], v1 = vp[1];
        float dot = q0.x*k0.x + q0.y*k0.y + q0.z*k0.z + q0.w*k0.w
                  + q1.x*k1.x + q1.y*k1.y + q1.z*k1.z + q1.w*k1.w;
        dot += __shfl_xor_sync(0xffffffffu, dot, 1);
        dot += __shfl_xor_sync(0xffffffffu, dot, 2);
        dot += __shfl_xor_sync(0xffffffffu, dot, 4);
        // |alpha| ~ 1e-2 here, so softmax without max-shift is exact
        float ex = __expf(dot * 0.125f);
        den += ex;
        a0 += ex * v0.x; a1 += ex * v0.y; a2 += ex * v0.z; a3 += ex * v0.w;
        a4 += ex * v1.x; a5 += ex * v1.y; a6 += ex * v1.z; a7 += ex * v1.w;
    }
    float invden = (den > 0.f) ? (1.f / den) : 0.f;
    float o[8] = {a0*invden, a1*invden, a2*invden, a3*invden,
                  a4*invden, a5*invden, a6*invden, a7*invden};
    #pragma unroll
    for (int j = 0; j < 8; j++) {
        float t = o[j];
        t += __shfl_xor_sync(0xffffffffu, t, 8);
        t += __shfl_xor_sync(0xffffffffu, t, 16);
        o[j] = t * 0.25f;   // mean over 4 heads
    }
    const float4* xp = (const float4*)(g_xr + qslot * DDIM + cg * 8);
    float4 x0 = xp[0], x1 = xp[1];
    float xr[8] = {x0.x, x0.y, x0.z, x0.w, x1.x, x1.y, x1.z, x1.w};

    float part = 0.f;
    #pragma unroll
    for (int j = 0; j < 8; j++) {
        int c = cg * 8 + j;
        part += o[j] * Wbeta[c] + xr[j] * Wbeta[64 + c] + (o[j] - xr[j]) * Wbeta[128 + c];
    }
    part += __shfl_xor_sync(0xffffffffu, part, 1);
    part += __shfl_xor_sync(0xffffffffu, part, 2);
    part += __shfl_xor_sync(0xffffffffu, part, 4);
    float beta = 1.f / (1.f + __expf(-part));

    float hf[8];
    #pragma unroll
    for (int j = 0; j < 8; j++) hf[j] = beta * xr[j] + (1.f - beta) * o[j];

    if (lane < 8) {
        *(float4*)&g_hf[qslot * DDIM + cg * 8]     = make_float4(hf[0], hf[1], hf[2], hf[3]);
        *(float4*)&g_hf[qslot * DDIM + cg * 8 + 4] = make_float4(hf[4], hf[5], hf[6], hf[7]);
    }
}

// ---------------- final MLP head (warp per task) ----------------
__global__ void mlp_kernel(const int* __restrict__ task,
                           const float* __restrict__ W1, const float* __restrict__ b1,
                           const float* __restrict__ W2, const float* __restrict__ b2,
                           float* __restrict__ out) {
    __shared__ float W1s[64 * 32];
    __shared__ float W2s[32];
    __shared__ float b1s[32];
    int tid = threadIdx.x;
    for (int i = tid; i < 64 * 32; i += 128) W1s[i] = W1[i];
    if (tid < 32) { W2s[tid] = W2[tid]; b1s[tid] = b1[tid]; }
    __syncthreads();

    int warp = tid >> 5, lane = tid & 31;
    int t = blockIdx.x * 4 + warp;
    if (t >= N_TASK) return;
    int qslot = g_qslot[task[t]];
    float hv0 = g_hf[qslot * DDIM + lane];
    float hv1 = g_hf[qslot * DDIM + 32 + lane];
    float acc = b1s[lane];
    #pragma unroll
    for (int c = 0; c < 32; c++)
        acc = fmaf(__shfl_sync(0xffffffffu, hv0, c), W1s[c * 32 + lane], acc);
    #pragma unroll
    for (int c = 0; c < 32; c++)
        acc = fmaf(__shfl_sync(0xffffffffu, hv1, c), W1s[(32 + c) * 32 + lane], acc);
    float hid = fmaxf(acc, 0.f);
    float p = hid * W2s[lane];
    p += __shfl_xor_sync(0xffffffffu, p, 16);
    p += __shfl_xor_sync(0xffffffffu, p, 8);
    p += __shfl_xor_sync(0xffffffffu, p, 4);
    p += __shfl_xor_sync(0xffffffffu, p, 2);
    p += __shfl_xor_sync(0xffffffffu, p, 1);
    if (lane == 0) out[t] = 1.f / (1.f + __expf(-(p + b2[0])));
}

// ---------------- launch ----------------
extern "C" void kernel_launch(void* const* d_in, const int* in_sizes, int n_in,
                              void* d_out, int out_size) {
    const int*   x     = (const int*)  d_in[0];
    const int*   ei    = (const int*)  d_in[1];
    const int*   task  = (const int*)  d_in[2];
    const float* emb   = (const float*)d_in[3];
    const float* Wq    = (const float*)d_in[4];
    const float* bq    = (const float*)d_in[5];
    const float* Wk    = (const float*)d_in[6];
    const float* bk    = (const float*)d_in[7];
    const float* Wv    = (const float*)d_in[8];
    const float* bv    = (const float*)d_in[9];
    const float* Ws    = (const float*)d_in[10];
    const float* bs    = (const float*)d_in[11];
    const float* Wbeta = (const float*)d_in[12];
    const float* W1    = (const float*)d_in[13];
    const float* b1    = (const float*)d_in[14];
    const float* W2    = (const float*)d_in[15];
    const float* b2    = (const float*)d_in[16];
    float* out = (float*)d_out;

    const int* src = ei;            // edge_index[0]
    const int* dst = ei + N_EDGES;  // edge_index[1]

    zero_kernel   <<<(N_NODES + 255) / 256, 256>>>();
    flag_kernel   <<<(N_TASK  + 255) / 256, 256>>>(task);
    mark_kernel   <<<(N_EDGES + 255) / 256, 256>>>(src, dst);
    alloc_kernel  <<<(N_NODES + 255) / 256, 256>>>();
    scatter_kernel<<<(N_EDGES + 255) / 256, 256>>>(src, dst);

    dim3 gg((N_NODES + 63) / 64, 13);
    gemm_tc_kernel<<<gg, 128>>>(x, emb, Wq, bq, Wk, bk, Wv, bv, Ws, bs);

    aggregate_kernel<<<(MAXQ * 32 + 255) / 256, 256>>>(Wbeta);
    mlp_kernel<<<(N_TASK + 3) / 4, 128>>>(task, W1, b1, W2, b2, out);
}

// round 7
// speedup vs baseline: 5.8083x; 2.4368x over previous
#include <cuda_runtime.h>

#define N_NODES 50000
#define N_EDGES 200000
#define N_TASK  10000
#define VOCAB   1000
#define VPAD    1024   // padded row count for unguarded GEMM stores
#define DDIM    64
#define HC      256    // H*C = 4*64
#define MAXQ    N_TASK

// ---------------- scratch (device globals; no allocations) ----------------
// Per-VOCAB tables (tiny: ~3.4MB total, L2-resident)
__device__ __align__(16) float g_Q [VPAD * HC];
__device__ __align__(16) float g_K [VPAD * HC];
__device__ __align__(16) float g_V [VPAD * HC];
__device__ __align__(16) float g_XR[VPAD * DDIM];
// Per-node output (only flagged rows written)
__device__ __align__(16) float g_hf[N_NODES * DDIM];
__device__ int g_flag  [N_NODES];
__device__ int g_deg   [N_NODES];
__device__ int g_start [N_NODES];
__device__ int g_cursor[N_NODES];
__device__ int g_qlist [MAXQ];
__device__ int g_adj   [N_EDGES];    // vocab id of src, bucketed by flagged dst
__device__ int g_total_adj, g_cnt_q;

// ---------------- setup kernels ----------------
__global__ void zero_kernel() {
    int i = blockIdx.x * blockDim.x + threadIdx.x;
    if (i < N_NODES) { g_flag[i] = 0; g_deg[i] = 0; }
    if (i == 0) { g_total_adj = 0; g_cnt_q = 0; }
}

__global__ void flag_kernel(const int* __restrict__ task) {
    int t = blockIdx.x * blockDim.x + threadIdx.x;
    if (t < N_TASK) g_flag[task[t]] = 1;
}

__global__ void mark_kernel(const int* __restrict__ dstArr) {
    int e = blockIdx.x * blockDim.x + threadIdx.x;
    if (e < N_EDGES) {
        int dn = dstArr[e];
        if (g_flag[dn]) atomicAdd(&g_deg[dn], 1);
    }
}

// warp-aggregated bump allocator: adjacency ranges + flagged-node list
__global__ void alloc_kernel() {
    int i = blockIdx.x * blockDim.x + threadIdx.x;
    int lane = threadIdx.x & 31;
    unsigned full = 0xffffffffu;
    bool inb = (i < N_NODES);
    bool fl  = inb && g_flag[i];
    int deg  = fl ? g_deg[i] : 0;

    int incl = deg;
    #pragma unroll
    for (int o = 1; o < 32; o <<= 1) {
        int y = __shfl_up_sync(full, incl, o);
        if (lane >= o) incl += y;
    }
    int wsum = __shfl_sync(full, incl, 31);
    int base = 0;
    if (lane == 0 && wsum > 0) base = atomicAdd(&g_total_adj, wsum);
    base = __shfl_sync(full, base, 0);
    if (fl) {
        int st = base + incl - deg;
        g_start[i]  = st;
        g_cursor[i] = st;
    }
    unsigned bmq = __ballot_sync(full, fl);
    int qb = 0;
    if (lane == 0 && bmq) qb = atomicAdd(&g_cnt_q, __popc(bmq));
    qb = __shfl_sync(full, qb, 0);
    if (fl) g_qlist[qb + __popc(bmq & ((1u << lane) - 1u))] = i;
}

__global__ void scatter_kernel(const int* __restrict__ srcArr,
                               const int* __restrict__ dstArr,
                               const int* __restrict__ x) {
    int e = blockIdx.x * blockDim.x + threadIdx.x;
    if (e < N_EDGES) {
        int dn = dstArr[e];
        if (g_flag[dn]) {
            int p = atomicAdd(&g_cursor[dn], 1);
            g_adj[p] = x[srcArr[e]];   // store src's VOCAB id directly
        }
    }
}

// ---------------- tf32 tensor-core GEMM over the vocab table ----------------
__device__ __forceinline__ unsigned f2tf32(float f) {
    unsigned r;
    asm("cvt.rna.tf32.f32 %0, %1;" : "=r"(r) : "f"(f));
    return r;
}

__device__ __forceinline__ void mma_tf32(float c[4],
                                         unsigned a0, unsigned a1, unsigned a2, unsigned a3,
                                         unsigned b0, unsigned b1) {
    asm volatile(
        "mma.sync.aligned.m16n8k8.row.col.f32.tf32.tf32.f32 "
        "{%0,%1,%2,%3}, {%4,%5,%6,%7}, {%8,%9}, {%0,%1,%2,%3};"
        : "+f"(c[0]), "+f"(c[1]), "+f"(c[2]), "+f"(c[3])
        : "r"(a0), "r"(a1), "r"(a2), "r"(a3), "r"(b0), "r"(b1));
}

// Dense A = emb[0..999]. blockIdx.y: 0-3 q, 4 xr, 5-8 k, 9-12 v.
// 128 threads, 64x64x64 tile, tf32 mma.sync. Stores unguarded into VPAD rows.
__global__ __launch_bounds__(128) void gemm_tc_kernel(
    const float* __restrict__ emb,
    const float* __restrict__ Wq, const float* __restrict__ bq,
    const float* __restrict__ Wk, const float* __restrict__ bk,
    const float* __restrict__ Wv, const float* __restrict__ bv,
    const float* __restrict__ Ws, const float* __restrict__ bs)
{
    __shared__ __align__(16) unsigned As[64 * 68];
    __shared__ __align__(16) unsigned Bs[64 * 68];

    int by = blockIdx.y;
    const float* W; const float* bias; float* out; int ldw, ldo, colbase;
    if (by < 4)       { W = Wq; bias = bq; out = g_Q;  ldw = HC;   ldo = HC;   colbase = by * 64; }
    else if (by == 4) { W = Ws; bias = bs; out = g_XR; ldw = DDIM; ldo = DDIM; colbase = 0; }
    else if (by < 9)  { W = Wk; bias = bk; out = g_K;  ldw = HC;   ldo = HC;   colbase = (by - 5) * 64; }
    else              { W = Wv; bias = bv; out = g_V;  ldw = HC;   ldo = HC;   colbase = (by - 9) * 64; }

    int row0 = blockIdx.x * 64;
    int tid = threadIdx.x;
    // ---- load A: dense emb rows, tf32-converted; 2 threads per row ----
    {
        int r = tid >> 1, h = tid & 1;
        int gr = row0 + r;
        unsigned* dstp = &As[r * 68 + h * 32];
        if (gr < VOCAB) {
            const float4* srcp = (const float4*)(emb + gr * DDIM + h * 32);
            #pragma unroll
            for (int u = 0; u < 8; u++) {
                float4 v = srcp[u];
                uint4 o;
                o.x = f2tf32(v.x); o.y = f2tf32(v.y);
                o.z = f2tf32(v.z); o.w = f2tf32(v.w);
                *(uint4*)&dstp[u * 4] = o;
            }
        } else {
            uint4 z = make_uint4(0, 0, 0, 0);
            #pragma unroll
            for (int u = 0; u < 8; u++) *(uint4*)&dstp[u * 4] = z;
        }
    }
    // ---- load B ----
    {
        int k = tid >> 1, h = tid & 1;
        const float4* srcp = (const float4*)(W + k * ldw + colbase + h * 32);
        unsigned* dstp = &Bs[k * 68 + h * 32];
        #pragma unroll
        for (int u = 0; u < 8; u++) {
            float4 v = srcp[u];
            uint4 o;
            o.x = f2tf32(v.x); o.y = f2tf32(v.y);
            o.z = f2tf32(v.z); o.w = f2tf32(v.w);
            *(uint4*)&dstp[u * 4] = o;
        }
    }
    __syncthreads();

    int lane = tid & 31, w = tid >> 5;
    int g = lane >> 2, t = lane & 3;
    int mb = w * 16;

    float acc[8][4];
    #pragma unroll
    for (int j = 0; j < 8; j++)
        #pragma unroll
        for (int c = 0; c < 4; c++) acc[j][c] = 0.f;

    #pragma unroll
    for (int ks = 0; ks < 8; ks++) {
        int k0 = ks * 8;
        unsigned a0 = As[(mb + g)     * 68 + k0 + t];
        unsigned a1 = As[(mb + g + 8) * 68 + k0 + t];
        unsigned a2 = As[(mb + g)     * 68 + k0 + t + 4];
        unsigned a3 = As[(mb + g + 8) * 68 + k0 + t + 4];
        #pragma unroll
        for (int j = 0; j < 8; j++) {
            unsigned b0 = Bs[(k0 + t)     * 68 + j * 8 + g];
            unsigned b1 = Bs[(k0 + t + 4) * 68 + j * 8 + g];
            mma_tf32(acc[j], a0, a1, a2, a3, b0, b1);
        }
    }

    int gr0 = row0 + mb + g;   // < VPAD always; rows >= VOCAB are dead padding
    int gr1 = gr0 + 8;
    #pragma unroll
    for (int j = 0; j < 8; j++) {
        int n = colbase + j * 8 + t * 2;
        float bx = bias[n], byv = bias[n + 1];
        *(float2*)&out[gr0 * ldo + n] = make_float2(acc[j][0] + bx, acc[j][1] + byv);
        *(float2*)&out[gr1 * ldo + n] = make_float2(acc[j][2] + bx, acc[j][3] + byv);
    }
}

// ---------------- fused attention aggregate + skip gate (warp per flagged node) ----
__global__ void aggregate_kernel(const int* __restrict__ x,
                                 const float* __restrict__ Wbeta) {
    int slot = (blockIdx.x * blockDim.x + threadIdx.x) >> 5;
    if (slot >= g_cnt_q) return;
    int node = g_qlist[slot];
    int vx   = x[node];

    int lane = threadIdx.x & 31;
    int cg   = lane & 7;

    const float4* qp = (const float4*)(g_Q + vx * HC + lane * 8);
    float4 q0 = qp[0], q1 = qp[1];

    float a0=0,a1=0,a2=0,a3=0,a4=0,a5=0,a6=0,a7=0;
    float den = 0.f;
    int s = g_start[node];
    int d = g_deg[node];
    for (int e = 0; e < d; e++) {
        int sv = g_adj[s + e];   // vocab id of source
        const float4* kp = (const float4*)(g_K + sv * HC + lane * 8);
        float4 k0 = kp[0], k1 = kp[1];
        const float4* vp = (const float4*)(g_V + sv * HC + lane * 8);
        float4 v0 = vp[0], v1 = vp[1];
        float dot = q0.x*k0.x + q0.y*k0.y + q0.z*k0.z + q0.w*k0.w
                  + q1.x*k1.x + q1.y*k1.y + q1.z*k1.z + q1.w*k1.w;
        dot += __shfl_xor_sync(0xffffffffu, dot, 1);
        dot += __shfl_xor_sync(0xffffffffu, dot, 2);
        dot += __shfl_xor_sync(0xffffffffu, dot, 4);
        // |alpha| ~ 1e-2 here, so softmax without max-shift is exact
        float ex = __expf(dot * 0.125f);
        den += ex;
        a0 += ex * v0.x; a1 += ex * v0.y; a2 += ex * v0.z; a3 += ex * v0.w;
        a4 += ex * v1.x; a5 += ex * v1.y; a6 += ex * v1.z; a7 += ex * v1.w;
    }
    float invden = (den > 0.f) ? (1.f / den) : 0.f;
    float o[8] = {a0*invden, a1*invden, a2*invden, a3*invden,
                  a4*invden, a5*invden, a6*invden, a7*invden};
    #pragma unroll
    for (int j = 0; j < 8; j++) {
        float t = o[j];
        t += __shfl_xor_sync(0xffffffffu, t, 8);
        t += __shfl_xor_sync(0xffffffffu, t, 16);
        o[j] = t * 0.25f;   // mean over 4 heads
    }
    const float4* xp = (const float4*)(g_XR + vx * DDIM + cg * 8);
    float4 x0 = xp[0], x1 = xp[1];
    float xr[8] = {x0.x, x0.y, x0.z, x0.w, x1.x, x1.y, x1.z, x1.w};

    float part = 0.f;
    #pragma unroll
    for (int j = 0; j < 8; j++) {
        int c = cg * 8 + j;
        part += o[j] * Wbeta[c] + xr[j] * Wbeta[64 + c] + (o[j] - xr[j]) * Wbeta[128 + c];
    }
    part += __shfl_xor_sync(0xffffffffu, part, 1);
    part += __shfl_xor_sync(0xffffffffu, part, 2);
    part += __shfl_xor_sync(0xffffffffu, part, 4);
    float beta = 1.f / (1.f + __expf(-part));

    float hf[8];
    #pragma unroll
    for (int j = 0; j < 8; j++) hf[j] = beta * xr[j] + (1.f - beta) * o[j];

    if (lane < 8) {
        *(float4*)&g_hf[node * DDIM + cg * 8]     = make_float4(hf[0], hf[1], hf[2], hf[3]);
        *(float4*)&g_hf[node * DDIM + cg * 8 + 4] = make_float4(hf[4], hf[5], hf[6], hf[7]);
    }
}

// ---------------- final MLP head (warp per task) ----------------
__global__ void mlp_kernel(const int* __restrict__ task,
                           const float* __restrict__ W1, const float* __restrict__ b1,
                           const float* __restrict__ W2, const float* __restrict__ b2,
                           float* __restrict__ out) {
    __shared__ float W1s[64 * 32];
    __shared__ float W2s[32];
    __shared__ float b1s[32];
    int tid = threadIdx.x;
    for (int i = tid; i < 64 * 32; i += 128) W1s[i] = W1[i];
    if (tid < 32) { W2s[tid] = W2[tid]; b1s[tid] = b1[tid]; }
    __syncthreads();

    int warp = tid >> 5, lane = tid & 31;
    int t = blockIdx.x * 4 + warp;
    if (t >= N_TASK) return;
    int node = task[t];
    float hv0 = g_hf[node * DDIM + lane];
    float hv1 = g_hf[node * DDIM + 32 + lane];
    float acc = b1s[lane];
    #pragma unroll
    for (int c = 0; c < 32; c++)
        acc = fmaf(__shfl_sync(0xffffffffu, hv0, c), W1s[c * 32 + lane], acc);
    #pragma unroll
    for (int c = 0; c < 32; c++)
        acc = fmaf(__shfl_sync(0xffffffffu, hv1, c), W1s[(32 + c) * 32 + lane], acc);
    float hid = fmaxf(acc, 0.f);
    float p = hid * W2s[lane];
    p += __shfl_xor_sync(0xffffffffu, p, 16);
    p += __shfl_xor_sync(0xffffffffu, p, 8);
    p += __shfl_xor_sync(0xffffffffu, p, 4);
    p += __shfl_xor_sync(0xffffffffu, p, 2);
    p += __shfl_xor_sync(0xffffffffu, p, 1);
    if (lane == 0) out[t] = 1.f / (1.f + __expf(-(p + b2[0])));
}

// ---------------- launch ----------------
extern "C" void kernel_launch(void* const* d_in, const int* in_sizes, int n_in,
                              void* d_out, int out_size) {
    const int*   x     = (const int*)  d_in[0];
    const int*   ei    = (const int*)  d_in[1];
    const int*   task  = (const int*)  d_in[2];
    const float* emb   = (const float*)d_in[3];
    const float* Wq    = (const float*)d_in[4];
    const float* bq    = (const float*)d_in[5];
    const float* Wk    = (const float*)d_in[6];
    const float* bk    = (const float*)d_in[7];
    const float* Wv    = (const float*)d_in[8];
    const float* bv    = (const float*)d_in[9];
    const float* Ws    = (const float*)d_in[10];
    const float* bs    = (const float*)d_in[11];
    const float* Wbeta = (const float*)d_in[12];
    const float* W1    = (const float*)d_in[13];
    const float* b1    = (const float*)d_in[14];
    const float* W2    = (const float*)d_in[15];
    const float* b2    = (const float*)d_in[16];
    float* out = (float*)d_out;

    const int* src = ei;            // edge_index[0]
    const int* dst = ei + N_EDGES;  // edge_index[1]

    // vocab-table GEMM is independent of the setup chain; launch it first
    dim3 gg((VPAD + 63) / 64, 13);
    gemm_tc_kernel<<<gg, 128>>>(emb, Wq, bq, Wk, bk, Wv, bv, Ws, bs);

    zero_kernel   <<<(N_NODES + 255) / 256, 256>>>();
    flag_kernel   <<<(N_TASK  + 255) / 256, 256>>>(task);
    mark_kernel   <<<(N_EDGES + 255) / 256, 256>>>(dst);
    alloc_kernel  <<<(N_NODES + 255) / 256, 256>>>();
    scatter_kernel<<<(N_EDGES + 255) / 256, 256>>>(src, dst, x);

    aggregate_kernel<<<(MAXQ * 32 + 255) / 256, 256>>>(x, Wbeta);
    mlp_kernel<<<(N_TASK + 3) / 4, 128>>>(task, W1, b1, W2, b2, out);
}

// round 8
// speedup vs baseline: 7.4380x; 1.2806x over previous
#include <cuda_runtime.h>

#define N_NODES 50000
#define N_EDGES 200000
#define N_TASK  10000
#define VOCAB   1000
#define VPAD    1024   // padded row count for unguarded GEMM stores
#define DDIM    64
#define HC      256    // H*C = 4*64

// ---------------- scratch (device globals; no allocations) ----------------
// Per-VOCAB tables (~3.4MB total, L2-resident)
__device__ __align__(16) float g_Q [VPAD * HC];
__device__ __align__(16) float g_K [VPAD * HC];
__device__ __align__(16) float g_V [VPAD * HC];
__device__ __align__(16) float g_XR[VPAD * DDIM];
// per-dst linked list: head[node] -> edge chain; edge = {next, src_vocab}
__device__ int  g_head[N_NODES];
__device__ int2 g_edge[N_EDGES];

// ---------------- tf32 tensor-core GEMM over the vocab table ----------------
__device__ __forceinline__ unsigned f2tf32(float f) {
    unsigned r;
    asm("cvt.rna.tf32.f32 %0, %1;" : "=r"(r) : "f"(f));
    return r;
}

__device__ __forceinline__ void mma_tf32(float c[4],
                                         unsigned a0, unsigned a1, unsigned a2, unsigned a3,
                                         unsigned b0, unsigned b1) {
    asm volatile(
        "mma.sync.aligned.m16n8k8.row.col.f32.tf32.tf32.f32 "
        "{%0,%1,%2,%3}, {%4,%5,%6,%7}, {%8,%9}, {%0,%1,%2,%3};"
        : "+f"(c[0]), "+f"(c[1]), "+f"(c[2]), "+f"(c[3])
        : "r"(a0), "r"(a1), "r"(a2), "r"(a3), "r"(b0), "r"(b1));
}

// blockIdx.y: 0-3 q, 4 xr, 5-8 k, 9-12 v, 13 -> clear g_head (piggybacked init).
// 128 threads, 64x64x64 tile, tf32 mma.sync, unguarded stores into VPAD rows.
__global__ __launch_bounds__(128) void gemm_tc_kernel(
    const float* __restrict__ emb,
    const float* __restrict__ Wq, const float* __restrict__ bq,
    const float* __restrict__ Wk, const float* __restrict__ bk,
    const float* __restrict__ Wv, const float* __restrict__ bv,
    const float* __restrict__ Ws, const float* __restrict__ bs)
{
    int by = blockIdx.y;
    if (by == 13) {   // init pass: head = -1
        int tid = blockIdx.x * 128 + threadIdx.x;   // 16*128 = 2048 threads
        for (int i = tid; i < N_NODES; i += 2048) g_head[i] = -1;
        return;
    }

    __shared__ __align__(16) unsigned As[64 * 68];
    __shared__ __align__(16) unsigned Bs[64 * 68];

    const float* W; const float* bias; float* out; int ldw, ldo, colbase;
    if (by < 4)       { W = Wq; bias = bq; out = g_Q;  ldw = HC;   ldo = HC;   colbase = by * 64; }
    else if (by == 4) { W = Ws; bias = bs; out = g_XR; ldw = DDIM; ldo = DDIM; colbase = 0; }
    else if (by < 9)  { W = Wk; bias = bk; out = g_K;  ldw = HC;   ldo = HC;   colbase = (by - 5) * 64; }
    else              { W = Wv; bias = bv; out = g_V;  ldw = HC;   ldo = HC;   colbase = (by - 9) * 64; }

    int row0 = blockIdx.x * 64;
    int tid = threadIdx.x;
    // ---- load A: dense emb rows, tf32-converted; 2 threads per row ----
    {
        int r = tid >> 1, h = tid & 1;
        int gr = row0 + r;
        unsigned* dstp = &As[r * 68 + h * 32];
        if (gr < VOCAB) {
            const float4* srcp = (const float4*)(emb + gr * DDIM + h * 32);
            #pragma unroll
            for (int u = 0; u < 8; u++) {
                float4 v = srcp[u];
                uint4 o;
                o.x = f2tf32(v.x); o.y = f2tf32(v.y);
                o.z = f2tf32(v.z); o.w = f2tf32(v.w);
                *(uint4*)&dstp[u * 4] = o;
            }
        } else {
            uint4 z = make_uint4(0, 0, 0, 0);
            #pragma unroll
            for (int u = 0; u < 8; u++) *(uint4*)&dstp[u * 4] = z;
        }
    }
    // ---- load B ----
    {
        int k = tid >> 1, h = tid & 1;
        const float4* srcp = (const float4*)(W + k * ldw + colbase + h * 32);
        unsigned* dstp = &Bs[k * 68 + h * 32];
        #pragma unroll
        for (int u = 0; u < 8; u++) {
            float4 v = srcp[u];
            uint4 o;
            o.x = f2tf32(v.x); o.y = f2tf32(v.y);
            o.z = f2tf32(v.z); o.w = f2tf32(v.w);
            *(uint4*)&dstp[u * 4] = o;
        }
    }
    __syncthreads();

    int lane = tid & 31, w = tid >> 5;
    int g = lane >> 2, t = lane & 3;
    int mb = w * 16;

    float acc[8][4];
    #pragma unroll
    for (int j = 0; j < 8; j++)
        #pragma unroll
        for (int c = 0; c < 4; c++) acc[j][c] = 0.f;

    #pragma unroll
    for (int ks = 0; ks < 8; ks++) {
        int k0 = ks * 8;
        unsigned a0 = As[(mb + g)     * 68 + k0 + t];
        unsigned a1 = As[(mb + g + 8) * 68 + k0 + t];
        unsigned a2 = As[(mb + g)     * 68 + k0 + t + 4];
        unsigned a3 = As[(mb + g + 8) * 68 + k0 + t + 4];
        #pragma unroll
        for (int j = 0; j < 8; j++) {
            unsigned b0 = Bs[(k0 + t)     * 68 + j * 8 + g];
            unsigned b1 = Bs[(k0 + t + 4) * 68 + j * 8 + g];
            mma_tf32(acc[j], a0, a1, a2, a3, b0, b1);
        }
    }

    int gr0 = row0 + mb + g;   // < VPAD; rows >= VOCAB are dead padding
    int gr1 = gr0 + 8;
    #pragma unroll
    for (int j = 0; j < 8; j++) {
        int n = colbase + j * 8 + t * 2;
        float bx = bias[n], byv = bias[n + 1];
        *(float2*)&out[gr0 * ldo + n] = make_float2(acc[j][0] + bx, acc[j][1] + byv);
        *(float2*)&out[gr1 * ldo + n] = make_float2(acc[j][2] + bx, acc[j][3] + byv);
    }
}

// ---------------- single edge pass: per-dst linked-list insert ----------------
__global__ void build_kernel(const int* __restrict__ srcArr,
                             const int* __restrict__ dstArr,
                             const int* __restrict__ x) {
    int e = blockIdx.x * blockDim.x + threadIdx.x;
    if (e < N_EDGES) {
        int dn  = dstArr[e];
        int old = atomicExch(&g_head[dn], e);
        g_edge[e] = make_int2(old, x[srcArr[e]]);
    }
}

// ------- fused attention aggregate + skip gate + MLP head (warp per task) -----
__global__ __launch_bounds__(256) void task_kernel(
    const int*   __restrict__ x,     const int*   __restrict__ task,
    const float* __restrict__ Wbeta,
    const float* __restrict__ W1,    const float* __restrict__ b1,
    const float* __restrict__ W2,    const float* __restrict__ b2,
    float* __restrict__ out)
{
    __shared__ float W1s[64 * 32];
    __shared__ float W2s[32];
    __shared__ float b1s[32];
    int tid = threadIdx.x;
    for (int i = tid; i < 64 * 32; i += 256) W1s[i] = W1[i];
    if (tid < 32) { W2s[tid] = W2[tid]; b1s[tid] = b1[tid]; }
    __syncthreads();

    int warp = tid >> 5, lane = tid & 31;
    int t = blockIdx.x * 8 + warp;
    if (t >= N_TASK) return;
    int node = task[t];
    int vx   = x[node];

    int cg = lane & 7;   // lane = head*8 + cg; lane covers channels cg*8..cg*8+7

    const float4* qp = (const float4*)(g_Q + vx * HC + lane * 8);
    float4 q0 = qp[0], q1 = qp[1];

    float a0=0,a1=0,a2=0,a3=0,a4=0,a5=0,a6=0,a7=0;
    float den = 0.f;
    int e = g_head[node];
    while (e >= 0) {
        int2 ed = g_edge[e];       // {next, src vocab}
        int sv = ed.y;
        const float4* kp = (const float4*)(g_K + sv * HC + lane * 8);
        float4 k0 = kp[0], k1 = kp[1];
        const float4* vp = (const float4*)(g_V + sv * HC + lane * 8);
        float4 v0 = vp[0], v1 = vp[1];
        float dot = q0.x*k0.x + q0.y*k0.y + q0.z*k0.z + q0.w*k0.w
                  + q1.x*k1.x + q1.y*k1.y + q1.z*k1.z + q1.w*k1.w;
        dot += __shfl_xor_sync(0xffffffffu, dot, 1);
        dot += __shfl_xor_sync(0xffffffffu, dot, 2);
        dot += __shfl_xor_sync(0xffffffffu, dot, 4);
        // |alpha| ~ 1e-2 here, so softmax without max-shift is exact
        float ex = __expf(dot * 0.125f);
        den += ex;
        a0 += ex * v0.x; a1 += ex * v0.y; a2 += ex * v0.z; a3 += ex * v0.w;
        a4 += ex * v1.x; a5 += ex * v1.y; a6 += ex * v1.z; a7 += ex * v1.w;
        e = ed.x;
    }
    float invden = (den > 0.f) ? (1.f / den) : 0.f;
    float o[8] = {a0*invden, a1*invden, a2*invden, a3*invden,
                  a4*invden, a5*invden, a6*invden, a7*invden};
    #pragma unroll
    for (int j = 0; j < 8; j++) {
        float s = o[j];
        s += __shfl_xor_sync(0xffffffffu, s, 8);
        s += __shfl_xor_sync(0xffffffffu, s, 16);
        o[j] = s * 0.25f;   // mean over 4 heads (replicated on all head-groups)
    }
    const float4* xp = (const float4*)(g_XR + vx * DDIM + cg * 8);
    float4 x0 = xp[0], x1 = xp[1];
    float xr[8] = {x0.x, x0.y, x0.z, x0.w, x1.x, x1.y, x1.z, x1.w};

    float part = 0.f;
    #pragma unroll
    for (int j = 0; j < 8; j++) {
        int c = cg * 8 + j;
        part += o[j] * Wbeta[c] + xr[j] * Wbeta[64 + c] + (o[j] - xr[j]) * Wbeta[128 + c];
    }
    part += __shfl_xor_sync(0xffffffffu, part, 1);
    part += __shfl_xor_sync(0xffffffffu, part, 2);
    part += __shfl_xor_sync(0xffffffffu, part, 4);
    float beta = 1.f / (1.f + __expf(-part));

    float hf[8];
    #pragma unroll
    for (int j = 0; j < 8; j++) hf[j] = beta * xr[j] + (1.f - beta) * o[j];
    // hf[j] on lane with cg = lane&7 holds channel cg*8+j (replicated over head groups)

    // ---- fused MLP head: hidden[lane] = relu(sum_c h[c] * W1[c][lane] + b1) ----
    float acc = b1s[lane];
    #pragma unroll
    for (int c = 0; c < 64; c++) {
        float hc = __shfl_sync(0xffffffffu, hf[c & 7], c >> 3);
        acc = fmaf(hc, W1s[c * 32 + lane], acc);
    }
    float hid = fmaxf(acc, 0.f);
    float p = hid * W2s[lane];
    p += __shfl_xor_sync(0xffffffffu, p, 16);
    p += __shfl_xor_sync(0xffffffffu, p, 8);
    p += __shfl_xor_sync(0xffffffffu, p, 4);
    p += __shfl_xor_sync(0xffffffffu, p, 2);
    p += __shfl_xor_sync(0xffffffffu, p, 1);
    if (lane == 0) out[t] = 1.f / (1.f + __expf(-(p + b2[0])));
}

// ---------------- launch ----------------
extern "C" void kernel_launch(void* const* d_in, const int* in_sizes, int n_in,
                              void* d_out, int out_size) {
    const int*   x     = (const int*)  d_in[0];
    const int*   ei    = (const int*)  d_in[1];
    const int*   task  = (const int*)  d_in[2];
    const float* emb   = (const float*)d_in[3];
    const float* Wq    = (const float*)d_in[4];
    const float* bq    = (const float*)d_in[5];
    const float* Wk    = (const float*)d_in[6];
    const float* bk    = (const float*)d_in[7];
    const float* Wv    = (const float*)d_in[8];
    const float* bv    = (const float*)d_in[9];
    const float* Ws    = (const float*)d_in[10];
    const float* bs    = (const float*)d_in[11];
    const float* Wbeta = (const float*)d_in[12];
    const float* W1    = (const float*)d_in[13];
    const float* b1    = (const float*)d_in[14];
    const float* W2    = (const float*)d_in[15];
    const float* b2    = (const float*)d_in[16];
    float* out = (float*)d_out;

    const int* src = ei;            // edge_index[0]
    const int* dst = ei + N_EDGES;  // edge_index[1]

    // launch 1: vocab-table GEMMs + head-array init (piggybacked as by==13)
    dim3 gg((VPAD + 63) / 64, 14);
    gemm_tc_kernel<<<gg, 128>>>(emb, Wq, bq, Wk, bk, Wv, bv, Ws, bs);

    // launch 2: one edge pass -> per-dst linked lists
    build_kernel<<<(N_EDGES + 255) / 256, 256>>>(src, dst, x);

    // launch 3: fused attention + gate + MLP, one warp per task
    task_kernel<<<(N_TASK + 7) / 8, 256>>>(x, task, Wbeta, W1, b1, W2, b2, out);
}

// round 9
// speedup vs baseline: 8.0771x; 1.0859x over previous
#include <cuda_runtime.h>
#include <cuda_bf16.h>

#define N_NODES 50000
#define N_EDGES 200000
#define N_TASK  10000
#define VOCAB   1000
#define VPAD    1024   // padded row count for unguarded GEMM stores
#define DDIM    64
#define HC      256    // H*C = 4*64
#define HCP     128    // u32 (bf16x2) per table row

#define GEMM_BLOCKS (13 * 32)   // 13 col-variants x 32 row-tiles of 32 rows
#define INIT_BLOCKS 16

// ---------------- scratch (device globals; no allocations) ----------------
// Per-VOCAB tables: Q/K/V in packed bf16x2 (halves L2 traffic), XR fp32.
__device__ __align__(16) unsigned g_Qh[VPAD * HCP];
__device__ __align__(16) unsigned g_Kh[VPAD * HCP];
__device__ __align__(16) unsigned g_Vh[VPAD * HCP];
__device__ __align__(16) float    g_XR[VPAD * DDIM];
// per-dst linked list: head[node] -> edge chain; edge = {next, src_vocab}
__device__ int  g_head[N_NODES];
__device__ int2 g_edge[N_EDGES];

// ---------------- tf32 helpers ----------------
__device__ __forceinline__ unsigned f2tf32(float f) {
    unsigned r;
    asm("cvt.rna.tf32.f32 %0, %1;" : "=r"(r) : "f"(f));
    return r;
}

__device__ __forceinline__ void mma_tf32(float c[4],
                                         unsigned a0, unsigned a1, unsigned a2, unsigned a3,
                                         unsigned b0, unsigned b1) {
    asm volatile(
        "mma.sync.aligned.m16n8k8.row.col.f32.tf32.tf32.f32 "
        "{%0,%1,%2,%3}, {%4,%5,%6,%7}, {%8,%9}, {%0,%1,%2,%3};"
        : "+f"(c[0]), "+f"(c[1]), "+f"(c[2]), "+f"(c[3])
        : "r"(a0), "r"(a1), "r"(a2), "r"(a3), "r"(b0), "r"(b1));
}

__device__ __forceinline__ void unp8(uint4 u, float f[8]) {
    float2 p0 = __bfloat1622float2(*(__nv_bfloat162*)&u.x);
    float2 p1 = __bfloat1622float2(*(__nv_bfloat162*)&u.y);
    float2 p2 = __bfloat1622float2(*(__nv_bfloat162*)&u.z);
    float2 p3 = __bfloat1622float2(*(__nv_bfloat162*)&u.w);
    f[0]=p0.x; f[1]=p0.y; f[2]=p1.x; f[3]=p1.y;
    f[4]=p2.x; f[5]=p2.y; f[6]=p3.x; f[7]=p3.y;
}

// Flat 1D grid: blocks [0, GEMM_BLOCKS) compute, the rest init g_head = -1.
// Block tile: 32(M) x 64(N) x 64(K); 4 warps, each m16n32 (32 mma.m16n8k8).
// variant = bid/32: 0-3 q, 4 xr, 5-8 k, 9-12 v.
__global__ __launch_bounds__(128) void gemm_tc_kernel(
    const float* __restrict__ emb,
    const float* __restrict__ Wq, const float* __restrict__ bq,
    const float* __restrict__ Wk, const float* __restrict__ bk,
    const float* __restrict__ Wv, const float* __restrict__ bv,
    const float* __restrict__ Ws, const float* __restrict__ bs)
{
    int bid = blockIdx.x;
    if (bid >= GEMM_BLOCKS) {   // init pass: head = -1
        int idx = (bid - GEMM_BLOCKS) * 128 + threadIdx.x;
        for (int i = idx; i < N_NODES; i += INIT_BLOCKS * 128) g_head[i] = -1;
        return;
    }

    __shared__ __align__(16) unsigned As[32 * 68];
    __shared__ __align__(16) unsigned Bs[64 * 68];

    int variant = bid >> 5;
    int row0    = (bid & 31) * 32;

    const float* W; const float* bias; int ldw, colbase;
    unsigned* outh = 0; float* outf = 0;
    if (variant < 4)       { W = Wq; bias = bq; outh = g_Qh; ldw = HC;   colbase = variant * 64; }
    else if (variant == 4) { W = Ws; bias = bs; outf = g_XR; ldw = DDIM; colbase = 0; }
    else if (variant < 9)  { W = Wk; bias = bk; outh = g_Kh; ldw = HC;   colbase = (variant - 5) * 64; }
    else                   { W = Wv; bias = bv; outh = g_Vh; ldw = HC;   colbase = (variant - 9) * 64; }

    int tid = threadIdx.x;
    // ---- load A: 32 dense emb rows, tf32-converted; 4 threads per row ----
    {
        int r = tid >> 2, q4 = tid & 3;
        int gr = row0 + r;
        unsigned* dstp = &As[r * 68 + q4 * 16];
        if (gr < VOCAB) {
            const float4* srcp = (const float4*)(emb + gr * DDIM + q4 * 16);
            #pragma unroll
            for (int u = 0; u < 4; u++) {
                float4 v = srcp[u];
                uint4 o;
                o.x = f2tf32(v.x); o.y = f2tf32(v.y);
                o.z = f2tf32(v.z); o.w = f2tf32(v.w);
                *(uint4*)&dstp[u * 4] = o;
            }
        } else {
            uint4 z = make_uint4(0, 0, 0, 0);
            #pragma unroll
            for (int u = 0; u < 4; u++) *(uint4*)&dstp[u * 4] = z;
        }
    }
    // ---- load B: 64(k) x 64(n); 2 threads per k-row ----
    {
        int k = tid >> 1, h = tid & 1;
        const float4* srcp = (const float4*)(W + k * ldw + colbase + h * 32);
        unsigned* dstp = &Bs[k * 68 + h * 32];
        #pragma unroll
        for (int u = 0; u < 8; u++) {
            float4 v = srcp[u];
            uint4 o;
            o.x = f2tf32(v.x); o.y = f2tf32(v.y);
            o.z = f2tf32(v.z); o.w = f2tf32(v.w);
            *(uint4*)&dstp[u * 4] = o;
        }
    }
    __syncthreads();

    int lane = tid & 31, w = tid >> 5;
    int g = lane >> 2, t = lane & 3;
    int mb = (w & 1) * 16;      // row half
    int cb = (w >> 1) * 32;     // col half

    float acc[4][4];
    #pragma unroll
    for (int j = 0; j < 4; j++)
        #pragma unroll
        for (int c = 0; c < 4; c++) acc[j][c] = 0.f;

    #pragma unroll
    for (int ks = 0; ks < 8; ks++) {
        int k0 = ks * 8;
        unsigned a0 = As[(mb + g)     * 68 + k0 + t];
        unsigned a1 = As[(mb + g + 8) * 68 + k0 + t];
        unsigned a2 = As[(mb + g)     * 68 + k0 + t + 4];
        unsigned a3 = As[(mb + g + 8) * 68 + k0 + t + 4];
        #pragma unroll
        for (int j = 0; j < 4; j++) {
            int jc = cb + j * 8 + g;
            unsigned b0 = Bs[(k0 + t)     * 68 + jc];
            unsigned b1 = Bs[(k0 + t + 4) * 68 + jc];
            mma_tf32(acc[j], a0, a1, a2, a3, b0, b1);
        }
    }

    int gr0 = row0 + mb + g;   // < VPAD; rows >= VOCAB are dead padding
    int gr1 = gr0 + 8;
    #pragma unroll
    for (int j = 0; j < 4; j++) {
        int n = colbase + cb + j * 8 + t * 2;
        float bx = bias[n], byv = bias[n + 1];
        if (variant == 4) {
            *(float2*)&outf[gr0 * DDIM + n] = make_float2(acc[j][0] + bx, acc[j][1] + byv);
            *(float2*)&outf[gr1 * DDIM + n] = make_float2(acc[j][2] + bx, acc[j][3] + byv);
        } else {
            __nv_bfloat162 h0 = __float22bfloat162_rn(make_float2(acc[j][0] + bx, acc[j][1] + byv));
            __nv_bfloat162 h1 = __float22bfloat162_rn(make_float2(acc[j][2] + bx, acc[j][3] + byv));
            outh[gr0 * HCP + (n >> 1)] = *(unsigned*)&h0;
            outh[gr1 * HCP + (n >> 1)] = *(unsigned*)&h1;
        }
    }
}

// ---------------- single edge pass: per-dst linked-list insert ----------------
__global__ void build_kernel(const int* __restrict__ srcArr,
                             const int* __restrict__ dstArr,
                             const int* __restrict__ x) {
    int e = blockIdx.x * blockDim.x + threadIdx.x;
    if (e < N_EDGES) {
        int dn  = dstArr[e];
        int old = atomicExch(&g_head[dn], e);
        g_edge[e] = make_int2(old, x[srcArr[e]]);
    }
}

// ------- fused attention aggregate + skip gate + MLP head (warp per task) -----
__global__ __launch_bounds__(256) void task_kernel(
    const int*   __restrict__ x,     const int*   __restrict__ task,
    const float* __restrict__ Wbeta,
    const float* __restrict__ W1,    const float* __restrict__ b1,
    const float* __restrict__ W2,    const float* __restrict__ b2,
    float* __restrict__ out)
{
    __shared__ float W1s[64 * 32];
    __shared__ float W2s[32];
    __shared__ float b1s[32];
    int tid = threadIdx.x;
    for (int i = tid; i < 64 * 32; i += 256) W1s[i] = W1[i];
    if (tid < 32) { W2s[tid] = W2[tid]; b1s[tid] = b1[tid]; }
    __syncthreads();

    int warp = tid >> 5, lane = tid & 31;
    int t = blockIdx.x * 8 + warp;
    if (t >= N_TASK) return;
    int node = task[t];
    int vx   = x[node];

    int cg = lane & 7;   // lane = head*8 + cg; lane covers channels cg*8..cg*8+7

    float qf[8];
    unp8(*(const uint4*)(g_Qh + vx * HCP + lane * 4), qf);

    float af[8] = {0, 0, 0, 0, 0, 0, 0, 0};
    float den = 0.f;
    int e = g_head[node];
    while (e >= 0) {
        int2 ed = g_edge[e];       // {next, src vocab}
        int sv = ed.y;
        float kf[8], vf[8];
        unp8(*(const uint4*)(g_Kh + sv * HCP + lane * 4), kf);
        unp8(*(const uint4*)(g_Vh + sv * HCP + lane * 4), vf);
        float dot = qf[0]*kf[0] + qf[1]*kf[1] + qf[2]*kf[2] + qf[3]*kf[3]
                  + qf[4]*kf[4] + qf[5]*kf[5] + qf[6]*kf[6] + qf[7]*kf[7];
        dot += __shfl_xor_sync(0xffffffffu, dot, 1);
        dot += __shfl_xor_sync(0xffffffffu, dot, 2);
        dot += __shfl_xor_sync(0xffffffffu, dot, 4);
        // |alpha| ~ 1e-2 here, so softmax without max-shift is exact
        float ex = __expf(dot * 0.125f);
        den += ex;
        #pragma unroll
        for (int j = 0; j < 8; j++) af[j] += ex * vf[j];
        e = ed.x;
    }
    float invden = (den > 0.f) ? (1.f / den) : 0.f;
    float o[8];
    #pragma unroll
    for (int j = 0; j < 8; j++) {
        float s = af[j] * invden;
        s += __shfl_xor_sync(0xffffffffu, s, 8);
        s += __shfl_xor_sync(0xffffffffu, s, 16);
        o[j] = s * 0.25f;   // mean over 4 heads (replicated on all head-groups)
    }
    const float4* xp = (const float4*)(g_XR + vx * DDIM + cg * 8);
    float4 x0 = xp[0], x1 = xp[1];
    float xr[8] = {x0.x, x0.y, x0.z, x0.w, x1.x, x1.y, x1.z, x1.w};

    float part = 0.f;
    #pragma unroll
    for (int j = 0; j < 8; j++) {
        int c = cg * 8 + j;
        part += o[j] * Wbeta[c] + xr[j] * Wbeta[64 + c] + (o[j] - xr[j]) * Wbeta[128 + c];
    }
    part += __shfl_xor_sync(0xffffffffu, part, 1);
    part += __shfl_xor_sync(0xffffffffu, part, 2);
    part += __shfl_xor_sync(0xffffffffu, part, 4);
    float beta = 1.f / (1.f + __expf(-part));

    float hf[8];
    #pragma unroll
    for (int j = 0; j < 8; j++) hf[j] = beta * xr[j] + (1.f - beta) * o[j];
    // hf[j] on lane with cg = lane&7 holds channel cg*8+j (replicated over head groups)

    // ---- fused MLP head: hidden[lane] = relu(sum_c h[c] * W1[c][lane] + b1) ----
    float acc = b1s[lane];
    #pragma unroll
    for (int c = 0; c < 64; c++) {
        float hc = __shfl_sync(0xffffffffu, hf[c & 7], c >> 3);
        acc = fmaf(hc, W1s[c * 32 + lane], acc);
    }
    float hid = fmaxf(acc, 0.f);
    float p = hid * W2s[lane];
    p += __shfl_xor_sync(0xffffffffu, p, 16);
    p += __shfl_xor_sync(0xffffffffu, p, 8);
    p += __shfl_xor_sync(0xffffffffu, p, 4);
    p += __shfl_xor_sync(0xffffffffu, p, 2);
    p += __shfl_xor_sync(0xffffffffu, p, 1);
    if (lane == 0) out[t] = 1.f / (1.f + __expf(-(p + b2[0])));
}

// ---------------- launch ----------------
extern "C" void kernel_launch(void* const* d_in, const int* in_sizes, int n_in,
                              void* d_out, int out_size) {
    const int*   x     = (const int*)  d_in[0];
    const int*   ei    = (const int*)  d_in[1];
    const int*   task  = (const int*)  d_in[2];
    const float* emb   = (const float*)d_in[3];
    const float* Wq    = (const float*)d_in[4];
    const float* bq    = (const float*)d_in[5];
    const float* Wk    = (const float*)d_in[6];
    const float* bk    = (const float*)d_in[7];
    const float* Wv    = (const float*)d_in[8];
    const float* bv    = (const float*)d_in[9];
    const float* Ws    = (const float*)d_in[10];
    const float* bs    = (const float*)d_in[11];
    const float* Wbeta = (const float*)d_in[12];
    const float* W1    = (const float*)d_in[13];
    const float* b1    = (const float*)d_in[14];
    const float* W2    = (const float*)d_in[15];
    const float* b2    = (const float*)d_in[16];
    float* out = (float*)d_out;

    const int* src = ei;            // edge_index[0]
    const int* dst = ei + N_EDGES;  // edge_index[1]

    // launch 1: vocab-table GEMMs + head-array init (piggybacked tail blocks)
    gemm_tc_kernel<<<GEMM_BLOCKS + INIT_BLOCKS, 128>>>(
        emb, Wq, bq, Wk, bk, Wv, bv, Ws, bs);

    // launch 2: one edge pass -> per-dst linked lists
    build_kernel<<<(N_EDGES + 255) / 256, 256>>>(src, dst, x);

    // launch 3: fused attention + gate + MLP, one warp per task
    task_kernel<<<(N_TASK + 7) / 8, 256>>>(x, task, Wbeta, W1, b1, W2, b2, out);
}